// round 2
// baseline (speedup 1.0000x reference)
#include <cuda_runtime.h>
#include <math.h>

// Problem constants (fixed shapes from reference)
#define B_    8
#define L_    2048
#define D_    256
#define N_    16
#define R_    16
#define NPROJ 80          // 64 (W_xproj rows) + 16 (W_xbproj rows)
#define CL    32          // scan chunk length
#define NC    (L_/CL)     // 64 chunks

// ---------------- scratch (device globals: no allocation allowed) ----------
__device__ float g_delta  [B_*L_*D_];      // softplus(delta_r @ Wdt^T + b)
__device__ float g_delta_b[B_*L_*D_];      // flipped-time variant
__device__ float g_BC     [B_*L_*48];      // Bf(16) Bb(16) C(16) per (b,l)
__device__ float g_P      [B_*NC*N_*D_];   // per-chunk decay product   [b][c][n][d]
__device__ float g_H      [B_*NC*N_*D_];   // per-chunk local end state [b][c][n][d]
__device__ float g_hs     [B_*NC*N_*D_];   // per-chunk start state     [b][c][n][d]
__device__ float g_y      [B_*L_*D_];      // scan output + skip

__device__ __forceinline__ float softplusf(float v) {
    // jax.nn.softplus = log1p(exp(v)), with overflow guard
    return v > 20.0f ? v : log1pf(__expf(v));
}

// ---------------------------------------------------------------------------
// Kernel 1: fused projections.
// Per block: 16 consecutive (b,l) rows.
//   p[j] = dot(x_row, Wrow_j), j<64 from W_xproj, 64..79 from W_xbproj
//   delta   = softplus(p[0:16]  @ Wdt^T + b)  -> g_delta[b,l]
//   delta_b = softplus(p[64:80] @ Wdt^T + b)  -> g_delta_b[b, L-1-l]  (flip!)
//   Bf,Bb,C = p[16:64]                        -> g_BC[b,l]
// ---------------------------------------------------------------------------
__global__ __launch_bounds__(256) void proj_kernel(
    const float* __restrict__ x, const float* __restrict__ Wxp,
    const float* __restrict__ Wxb, const float* __restrict__ Wdt,
    const float* __restrict__ bdt)
{
    const int ROWS = 16;
    __shared__ float sx[ROWS][D_];      // 16 KB
    __shared__ float sp[ROWS][NPROJ];   // 5 KB
    __shared__ float sWdtT[R_][D_];     // 16 KB (transposed W_dt)

    const int row0 = blockIdx.x * ROWS; // global row m = b*L + l
    const int tid  = threadIdx.x;

    // load W_dt transposed (conflict-free reads later)
    for (int i = tid; i < D_*R_; i += 256) {
        int d = i / R_, r = i % R_;
        sWdtT[r][d] = Wdt[i];
    }
    // load 16 x-rows
    for (int i = tid; i < ROWS*D_; i += 256)
        sx[i >> 8][i & 255] = x[row0*D_ + i];
    __syncthreads();

    // Stage A: 80 projection outputs per row. 8 warps x 10 outputs each.
    const int warp = tid >> 5, lane = tid & 31;
    #pragma unroll
    for (int t = 0; t < 10; ++t) {
        int j = warp + 8*t;                                   // 0..79
        const float* Wrow = (j < 64) ? (Wxp + j*D_) : (Wxb + (j-64)*D_);
        float wv[8];
        #pragma unroll
        for (int k = 0; k < 8; ++k) wv[k] = __ldg(Wrow + lane + 32*k);
        for (int r = 0; r < ROWS; ++r) {
            float acc = 0.f;
            #pragma unroll
            for (int k = 0; k < 8; ++k) acc = fmaf(wv[k], sx[r][lane + 32*k], acc);
            #pragma unroll
            for (int o = 16; o; o >>= 1) acc += __shfl_xor_sync(0xffffffffu, acc, o);
            if (lane == 0) sp[r][j] = acc;
        }
    }
    __syncthreads();

    // write Bf/Bb/C
    for (int i = tid; i < ROWS*48; i += 256) {
        int r = i / 48, c = i - r*48;
        g_BC[(row0 + r)*48 + c] = sp[r][16 + c];
    }

    // Stage B: dt projections + softplus (thread = output channel d)
    float wdt[R_];
    #pragma unroll
    for (int q = 0; q < R_; ++q) wdt[q] = sWdtT[q][tid];
    const float bv = bdt[tid];

    for (int r = 0; r < ROWS; ++r) {
        float s = bv, sb = bv;
        #pragma unroll
        for (int q = 0; q < R_; ++q) {
            s  = fmaf(sp[r][q],      wdt[q], s);
            sb = fmaf(sp[r][64 + q], wdt[q], sb);
        }
        const int m = row0 + r;
        const int b = m >> 11;            // L_ = 2048
        const int l = m & (L_ - 1);
        g_delta[m*D_ + tid]                              = softplusf(s);
        g_delta_b[((b << 11) + (L_ - 1 - l))*D_ + tid]   = softplusf(sb);
    }
}

// ---------------------------------------------------------------------------
// Kernel 2: scan pass 1 — per chunk compute P = prod(dA), H = local end state.
// Block = (b, chunk). Thread = d channel, holds h[16], p[16] in regs.
// ---------------------------------------------------------------------------
__global__ __launch_bounds__(256) void scan1_kernel(
    const float* __restrict__ x, const float* __restrict__ A_log)
{
    const int bc = blockIdx.x;
    const int b = bc / NC, c = bc - b*NC;
    const int d = threadIdx.x;
    const int l0 = c * CL;

    __shared__ float sB[CL][32];   // Bf,Bb per step (4 KB)
    for (int i = d; i < CL*32; i += 256) {
        int t = i >> 5, j = i & 31;
        sB[t][j] = g_BC[(b*L_ + l0 + t)*48 + j];   // cols [0:32) = Bf,Bb  (FIXED)
    }
    __syncthreads();

    float a[N_];
    #pragma unroll
    for (int n = 0; n < N_; ++n) a[n] = -__expf(A_log[d*N_ + n]);

    float h[N_], p[N_];
    #pragma unroll
    for (int n = 0; n < N_; ++n) { h[n] = 0.f; p[n] = 1.f; }

    const float* dl_ptr  = g_delta   + (b*L_ + l0)*D_ + d;
    const float* dlb_ptr = g_delta_b + (b*L_ + l0)*D_ + d;
    const float* x_ptr   = x + (b*L_ + l0)*D_ + d;
    const float* xr_ptr  = x + (b*L_ + (L_ - 1 - l0))*D_ + d;

    #pragma unroll 2
    for (int t = 0; t < CL; ++t) {
        const float dl  = dl_ptr[t*D_];
        const float dlb = dlb_ptr[t*D_];
        const float xv  = x_ptr[t*D_];
        const float xr  = xr_ptr[-t*D_];
        const float c1 = dl * xv, c2 = dlb * xr;
        #pragma unroll
        for (int n = 0; n < N_; ++n) {
            const float e  = __expf(dl * a[n]);
            const float du = fmaf(c1, sB[t][n], c2 * sB[t][16 + n]);
            h[n] = fmaf(e, h[n], du);
            p[n] *= e;
        }
    }

    float* Pp = g_P + ((b*NC + c)*N_)*D_ + d;
    float* Hp = g_H + ((b*NC + c)*N_)*D_ + d;
    #pragma unroll
    for (int n = 0; n < N_; ++n) { Pp[n*D_] = p[n]; Hp[n*D_] = h[n]; }
}

// ---------------------------------------------------------------------------
// Kernel 3: sequential combine across chunks (tiny).
// Thread = (b,n,d). 64-step loop: hs[c] stored, then hs = P[c]*hs + H[c].
// ---------------------------------------------------------------------------
__global__ __launch_bounds__(256) void combine_kernel()
{
    const int idx = blockIdx.x*256 + threadIdx.x;   // B_*N_*D_ = 32768
    const int d = idx & (D_ - 1);
    const int n = (idx >> 8) & (N_ - 1);
    const int b = idx >> 12;
    float hs = 0.f;
    for (int c = 0; c < NC; ++c) {
        const int off = ((b*NC + c)*N_ + n)*D_ + d;
        g_hs[off] = hs;
        hs = fmaf(g_P[off], hs, g_H[off]);
    }
}

// ---------------------------------------------------------------------------
// Kernel 4: scan pass 2 — recompute recurrence with correct initial state,
// emit y[l,d] = <h_l, C_l> + (x + xf)*D_skip.
// ---------------------------------------------------------------------------
__global__ __launch_bounds__(256) void scan2_kernel(
    const float* __restrict__ x, const float* __restrict__ A_log,
    const float* __restrict__ Dskip)
{
    const int bc = blockIdx.x;
    const int b = bc / NC, c = bc - b*NC;
    const int d = threadIdx.x;
    const int l0 = c * CL;

    __shared__ float sB[CL][48];   // Bf,Bb,C (6 KB)
    for (int i = d; i < CL*48; i += 256) {
        int t = i / 48, j = i - t*48;
        sB[t][j] = g_BC[(b*L_ + l0 + t)*48 + j];
    }
    __syncthreads();

    float a[N_];
    #pragma unroll
    for (int n = 0; n < N_; ++n) a[n] = -__expf(A_log[d*N_ + n]);

    float h[N_];
    #pragma unroll
    for (int n = 0; n < N_; ++n)
        h[n] = g_hs[((b*NC + c)*N_ + n)*D_ + d];

    const float dsk = Dskip[d];
    const float* dl_ptr  = g_delta   + (b*L_ + l0)*D_ + d;
    const float* dlb_ptr = g_delta_b + (b*L_ + l0)*D_ + d;
    const float* x_ptr   = x + (b*L_ + l0)*D_ + d;
    const float* xr_ptr  = x + (b*L_ + (L_ - 1 - l0))*D_ + d;
    float* y_ptr = g_y + (b*L_ + l0)*D_ + d;

    #pragma unroll 2
    for (int t = 0; t < CL; ++t) {
        const float dl  = dl_ptr[t*D_];
        const float dlb = dlb_ptr[t*D_];
        const float xv  = x_ptr[t*D_];
        const float xr  = xr_ptr[-t*D_];
        const float c1 = dl * xv, c2 = dlb * xr;
        float y = 0.f;
        #pragma unroll
        for (int n = 0; n < N_; ++n) {
            const float e  = __expf(dl * a[n]);
            const float du = fmaf(c1, sB[t][n], c2 * sB[t][16 + n]);
            h[n] = fmaf(e, h[n], du);
            y    = fmaf(h[n], sB[t][32 + n], y);
        }
        y_ptr[t*D_] = fmaf(xv + xr, dsk, y);
    }
}

// ---------------------------------------------------------------------------
// Kernel 5: out = y @ W_out^T.  M=16384, N=256, K=256, fp32 SIMT GEMM.
// Block tile 128(M) x 64(N), K-tile 16, 256 threads, 8x4 microtile.
// ---------------------------------------------------------------------------
__global__ __launch_bounds__(256) void gemm_kernel(
    float* __restrict__ out, const float* __restrict__ Wout)
{
    __shared__ float As[16][128];   // A^T: As[k][m]   (8 KB)
    __shared__ float Bs[16][64];    // B^T: Bs[k][j]   (4 KB)

    const int j0 = blockIdx.x * 64;     // N block (0..3)
    const int m0 = blockIdx.y * 128;    // M block (0..127)
    const int tid = threadIdx.x;
    const int tx = tid & 15;            // N direction
    const int ty = tid >> 4;            // M direction

    float acc[8][4];
    #pragma unroll
    for (int i = 0; i < 8; ++i)
        #pragma unroll
        for (int u = 0; u < 4; ++u) acc[i][u] = 0.f;

    const int av = tid;                  // A-load: 2 float4 per thread
    const int arow0 = av >> 2, ac4 = av & 3;           // +64 -> second
    const int bv = tid;                  // B-load: 1 float4 per thread
    const int brow = bv >> 2, bc4 = bv & 3;

    for (int k0 = 0; k0 < 256; k0 += 16) {
        // load A tile (y) transposed into smem
        #pragma unroll
        for (int it = 0; it < 2; ++it) {
            const int row = arow0 + it*64;
            const float4 v = *reinterpret_cast<const float4*>(
                g_y + (m0 + row)*D_ + k0 + ac4*4);
            As[ac4*4 + 0][row] = v.x;
            As[ac4*4 + 1][row] = v.y;
            As[ac4*4 + 2][row] = v.z;
            As[ac4*4 + 3][row] = v.w;
        }
        // load B tile (W_out) transposed into smem
        {
            const float4 v = *reinterpret_cast<const float4*>(
                Wout + (j0 + brow)*D_ + k0 + bc4*4);
            Bs[bc4*4 + 0][brow] = v.x;
            Bs[bc4*4 + 1][brow] = v.y;
            Bs[bc4*4 + 2][brow] = v.z;
            Bs[bc4*4 + 3][brow] = v.w;
        }
        __syncthreads();

        #pragma unroll
        for (int kk = 0; kk < 16; ++kk) {
            const float4 a0 = *reinterpret_cast<const float4*>(&As[kk][ty*8]);
            const float4 a1 = *reinterpret_cast<const float4*>(&As[kk][ty*8 + 4]);
            const float4 b  = *reinterpret_cast<const float4*>(&Bs[kk][tx*4]);
            const float am[8] = {a0.x,a0.y,a0.z,a0.w,a1.x,a1.y,a1.z,a1.w};
            const float bm[4] = {b.x,b.y,b.z,b.w};
            #pragma unroll
            for (int i = 0; i < 8; ++i)
                #pragma unroll
                for (int u = 0; u < 4; ++u)
                    acc[i][u] = fmaf(am[i], bm[u], acc[i][u]);
        }
        __syncthreads();
    }

    #pragma unroll
    for (int i = 0; i < 8; ++i) {
        float4 v = make_float4(acc[i][0], acc[i][1], acc[i][2], acc[i][3]);
        *reinterpret_cast<float4*>(out + (m0 + ty*8 + i)*D_ + j0 + tx*4) = v;
    }
}

// ---------------------------------------------------------------------------
extern "C" void kernel_launch(void* const* d_in, const int* in_sizes, int n_in,
                              void* d_out, int out_size)
{
    const float* x     = (const float*)d_in[0];
    const float* Wxp   = (const float*)d_in[1];
    const float* Wxb   = (const float*)d_in[2];
    const float* Wdt   = (const float*)d_in[3];
    const float* bdt   = (const float*)d_in[4];
    const float* A_log = (const float*)d_in[5];
    const float* Dskip = (const float*)d_in[6];
    const float* Wout  = (const float*)d_in[7];
    float* out = (float*)d_out;

    proj_kernel   <<<(B_*L_)/16, 256>>>(x, Wxp, Wxb, Wdt, bdt);
    scan1_kernel  <<<B_*NC,      256>>>(x, A_log);
    combine_kernel<<<(B_*N_*D_)/256, 256>>>();
    scan2_kernel  <<<B_*NC,      256>>>(x, A_log, Dskip);
    gemm_kernel   <<<dim3(4, 128), 256>>>(out, Wout);
}

// round 3
// speedup vs baseline: 1.1114x; 1.1114x over previous
#include <cuda_runtime.h>
#include <math.h>

// Problem constants (fixed shapes from reference)
#define B_    8
#define L_    2048
#define D_    256
#define N_    16
#define R_    16
#define NPROJ 80          // 64 (W_xproj rows) + 16 (W_xbproj rows)
#define CL    32          // scan chunk length
#define NC    (L_/CL)     // 64 chunks

// ---------------- scratch (device globals: no allocation allowed) ----------
__device__ float g_delta  [B_*L_*D_];      // softplus(delta_r @ Wdt^T + b)
__device__ float g_delta_b[B_*L_*D_];      // flipped-time variant
__device__ float g_BC     [B_*L_*48];      // Bf(16) Bb(16) C(16) per (b,l)
__device__ float g_P      [B_*NC*N_*D_];   // per-chunk decay product   [b][c][n][d]
__device__ float g_H      [B_*NC*N_*D_];   // per-chunk local end state [b][c][n][d]
__device__ float g_hs     [B_*NC*N_*D_];   // per-chunk start state     [b][c][n][d]
__device__ float g_y      [B_*L_*D_];      // scan output + skip

__device__ __forceinline__ float softplusf(float v) {
    return v > 20.0f ? v : log1pf(__expf(v));
}

// e[n] = p1^(n+1), n = 0..15, via binary power tree (max ~4 rounding steps)
__device__ __forceinline__ void powers16(float p1, float e[N_]) {
    e[0]  = p1;
    e[1]  = p1 * p1;        // ^2
    e[2]  = e[1] * p1;      // ^3
    e[3]  = e[1] * e[1];    // ^4
    e[4]  = e[3] * p1;      // ^5
    e[5]  = e[3] * e[1];    // ^6
    e[6]  = e[3] * e[2];    // ^7
    e[7]  = e[3] * e[3];    // ^8
    e[8]  = e[7] * p1;      // ^9
    e[9]  = e[7] * e[1];    // ^10
    e[10] = e[7] * e[2];    // ^11
    e[11] = e[7] * e[3];    // ^12
    e[12] = e[7] * e[4];    // ^13
    e[13] = e[7] * e[5];    // ^14
    e[14] = e[7] * e[6];    // ^15
    e[15] = e[7] * e[7];    // ^16
}

// Check if A row for channel d has the structure a[n] = a0*(n+1).
// Returns a0; sets fast flag.
__device__ __forceinline__ float check_A(const float* __restrict__ A_log,
                                         int d, bool& fast) {
    float a0 = -__expf(__ldg(A_log + d*N_));
    fast = true;
    #pragma unroll
    for (int n = 1; n < N_; ++n) {
        float an = -__expf(__ldg(A_log + d*N_ + n));
        fast = fast && (fabsf(an - a0*(float)(n+1)) <= 1e-4f*(float)(n+1));
    }
    return a0;
}

// ---------------------------------------------------------------------------
// Kernel 1: fused projections (unchanged).
// ---------------------------------------------------------------------------
__global__ __launch_bounds__(256) void proj_kernel(
    const float* __restrict__ x, const float* __restrict__ Wxp,
    const float* __restrict__ Wxb, const float* __restrict__ Wdt,
    const float* __restrict__ bdt)
{
    const int ROWS = 16;
    __shared__ float sx[ROWS][D_];
    __shared__ float sp[ROWS][NPROJ];
    __shared__ float sWdtT[R_][D_];

    const int row0 = blockIdx.x * ROWS;
    const int tid  = threadIdx.x;

    for (int i = tid; i < D_*R_; i += 256) {
        int d = i / R_, r = i % R_;
        sWdtT[r][d] = Wdt[i];
    }
    for (int i = tid; i < ROWS*D_; i += 256)
        sx[i >> 8][i & 255] = x[row0*D_ + i];
    __syncthreads();

    const int warp = tid >> 5, lane = tid & 31;
    #pragma unroll
    for (int t = 0; t < 10; ++t) {
        int j = warp + 8*t;
        const float* Wrow = (j < 64) ? (Wxp + j*D_) : (Wxb + (j-64)*D_);
        float wv[8];
        #pragma unroll
        for (int k = 0; k < 8; ++k) wv[k] = __ldg(Wrow + lane + 32*k);
        for (int r = 0; r < ROWS; ++r) {
            float acc = 0.f;
            #pragma unroll
            for (int k = 0; k < 8; ++k) acc = fmaf(wv[k], sx[r][lane + 32*k], acc);
            #pragma unroll
            for (int o = 16; o; o >>= 1) acc += __shfl_xor_sync(0xffffffffu, acc, o);
            if (lane == 0) sp[r][j] = acc;
        }
    }
    __syncthreads();

    for (int i = tid; i < ROWS*48; i += 256) {
        int r = i / 48, c = i - r*48;
        g_BC[(row0 + r)*48 + c] = sp[r][16 + c];
    }

    float wdt[R_];
    #pragma unroll
    for (int q = 0; q < R_; ++q) wdt[q] = sWdtT[q][tid];
    const float bv = bdt[tid];

    for (int r = 0; r < ROWS; ++r) {
        float s = bv, sb = bv;
        #pragma unroll
        for (int q = 0; q < R_; ++q) {
            s  = fmaf(sp[r][q],      wdt[q], s);
            sb = fmaf(sp[r][64 + q], wdt[q], sb);
        }
        const int m = row0 + r;
        const int b = m >> 11;
        const int l = m & (L_ - 1);
        g_delta[m*D_ + tid]                              = softplusf(s);
        g_delta_b[((b << 11) + (L_ - 1 - l))*D_ + tid]   = softplusf(sb);
    }
}

// ---------------------------------------------------------------------------
// Kernel 2: scan pass 1 — per chunk decay product P and local end state H.
// Fast path: 1 MUFU per step + power tree; P[n] = (prod e1)^(n+1).
// ---------------------------------------------------------------------------
__global__ __launch_bounds__(256) void scan1_kernel(
    const float* __restrict__ x, const float* __restrict__ A_log)
{
    const int bc = blockIdx.x;
    const int b = bc / NC, c = bc - b*NC;
    const int d = threadIdx.x;
    const int l0 = c * CL;

    __shared__ float sB[CL][32];
    for (int i = d; i < CL*32; i += 256) {
        int t = i >> 5, j = i & 31;
        sB[t][j] = g_BC[(b*L_ + l0 + t)*48 + j];
    }
    __syncthreads();

    bool fast;
    const float a0 = check_A(A_log, d, fast);

    float h[N_];
    #pragma unroll
    for (int n = 0; n < N_; ++n) h[n] = 0.f;

    const float* dl_ptr  = g_delta   + (b*L_ + l0)*D_ + d;
    const float* dlb_ptr = g_delta_b + (b*L_ + l0)*D_ + d;
    const float* x_ptr   = x + (b*L_ + l0)*D_ + d;
    const float* xr_ptr  = x + (b*L_ + (L_ - 1 - l0))*D_ + d;

    float* Pp = g_P + ((b*NC + c)*N_)*D_ + d;
    float* Hp = g_H + ((b*NC + c)*N_)*D_ + d;

    if (fast) {
        float p1 = 1.f;
        #pragma unroll
        for (int t0 = 0; t0 < CL; t0 += 4) {
            float dl[4], dlb[4], xv[4], xr[4];
            #pragma unroll
            for (int i = 0; i < 4; ++i) {
                dl[i]  = dl_ptr [(t0+i)*D_];
                dlb[i] = dlb_ptr[(t0+i)*D_];
                xv[i]  = x_ptr  [(t0+i)*D_];
                xr[i]  = xr_ptr [-(t0+i)*D_];
            }
            #pragma unroll
            for (int i = 0; i < 4; ++i) {
                const int t = t0 + i;
                const float e1 = __expf(dl[i] * a0);
                float e[N_]; powers16(e1, e);
                const float c1 = dl[i]*xv[i], c2 = dlb[i]*xr[i];
                #pragma unroll
                for (int n = 0; n < N_; ++n)
                    h[n] = fmaf(e[n], h[n], fmaf(c1, sB[t][n], c2 * sB[t][16+n]));
                p1 *= e1;
            }
        }
        float pw[N_]; powers16(p1, pw);
        #pragma unroll
        for (int n = 0; n < N_; ++n) { Pp[n*D_] = pw[n]; Hp[n*D_] = h[n]; }
    } else {
        float a[N_], p[N_];
        #pragma unroll
        for (int n = 0; n < N_; ++n) {
            a[n] = -__expf(__ldg(A_log + d*N_ + n));
            p[n] = 1.f;
        }
        for (int t = 0; t < CL; ++t) {
            const float dl  = dl_ptr[t*D_];
            const float dlb = dlb_ptr[t*D_];
            const float xv  = x_ptr[t*D_];
            const float xr  = xr_ptr[-t*D_];
            const float c1 = dl*xv, c2 = dlb*xr;
            #pragma unroll
            for (int n = 0; n < N_; ++n) {
                const float e = __expf(dl * a[n]);
                h[n] = fmaf(e, h[n], fmaf(c1, sB[t][n], c2 * sB[t][16+n]));
                p[n] *= e;
            }
        }
        #pragma unroll
        for (int n = 0; n < N_; ++n) { Pp[n*D_] = p[n]; Hp[n*D_] = h[n]; }
    }
}

// ---------------------------------------------------------------------------
// Kernel 3: sequential combine across chunks (unchanged).
// ---------------------------------------------------------------------------
__global__ __launch_bounds__(256) void combine_kernel()
{
    const int idx = blockIdx.x*256 + threadIdx.x;
    const int d = idx & (D_ - 1);
    const int n = (idx >> 8) & (N_ - 1);
    const int b = idx >> 12;
    float hs = 0.f;
    for (int c = 0; c < NC; ++c) {
        const int off = ((b*NC + c)*N_ + n)*D_ + d;
        g_hs[off] = hs;
        hs = fmaf(g_P[off], hs, g_H[off]);
    }
}

// ---------------------------------------------------------------------------
// Kernel 4: scan pass 2 — recurrence with carried initial state, emit y.
// ---------------------------------------------------------------------------
__global__ __launch_bounds__(256) void scan2_kernel(
    const float* __restrict__ x, const float* __restrict__ A_log,
    const float* __restrict__ Dskip)
{
    const int bc = blockIdx.x;
    const int b = bc / NC, c = bc - b*NC;
    const int d = threadIdx.x;
    const int l0 = c * CL;

    __shared__ float sB[CL][48];
    for (int i = d; i < CL*48; i += 256) {
        int t = i / 48, j = i - t*48;
        sB[t][j] = g_BC[(b*L_ + l0 + t)*48 + j];
    }
    __syncthreads();

    bool fast;
    const float a0 = check_A(A_log, d, fast);

    float h[N_];
    #pragma unroll
    for (int n = 0; n < N_; ++n)
        h[n] = g_hs[((b*NC + c)*N_ + n)*D_ + d];

    const float dsk = Dskip[d];
    const float* dl_ptr  = g_delta   + (b*L_ + l0)*D_ + d;
    const float* dlb_ptr = g_delta_b + (b*L_ + l0)*D_ + d;
    const float* x_ptr   = x + (b*L_ + l0)*D_ + d;
    const float* xr_ptr  = x + (b*L_ + (L_ - 1 - l0))*D_ + d;
    float* y_ptr = g_y + (b*L_ + l0)*D_ + d;

    if (fast) {
        #pragma unroll
        for (int t0 = 0; t0 < CL; t0 += 4) {
            float dl[4], dlb[4], xv[4], xr[4];
            #pragma unroll
            for (int i = 0; i < 4; ++i) {
                dl[i]  = dl_ptr [(t0+i)*D_];
                dlb[i] = dlb_ptr[(t0+i)*D_];
                xv[i]  = x_ptr  [(t0+i)*D_];
                xr[i]  = xr_ptr [-(t0+i)*D_];
            }
            #pragma unroll
            for (int i = 0; i < 4; ++i) {
                const int t = t0 + i;
                const float e1 = __expf(dl[i] * a0);
                float e[N_]; powers16(e1, e);
                const float c1 = dl[i]*xv[i], c2 = dlb[i]*xr[i];
                float y = 0.f;
                #pragma unroll
                for (int n = 0; n < N_; ++n) {
                    h[n] = fmaf(e[n], h[n], fmaf(c1, sB[t][n], c2 * sB[t][16+n]));
                    y    = fmaf(h[n], sB[t][32+n], y);
                }
                y_ptr[t*D_] = fmaf(xv[i] + xr[i], dsk, y);
            }
        }
    } else {
        float a[N_];
        #pragma unroll
        for (int n = 0; n < N_; ++n)
            a[n] = -__expf(__ldg(A_log + d*N_ + n));
        for (int t = 0; t < CL; ++t) {
            const float dl  = dl_ptr[t*D_];
            const float dlb = dlb_ptr[t*D_];
            const float xv  = x_ptr[t*D_];
            const float xr  = xr_ptr[-t*D_];
            const float c1 = dl*xv, c2 = dlb*xr;
            float y = 0.f;
            #pragma unroll
            for (int n = 0; n < N_; ++n) {
                const float e = __expf(dl * a[n]);
                h[n] = fmaf(e, h[n], fmaf(c1, sB[t][n], c2 * sB[t][16+n]));
                y    = fmaf(h[n], sB[t][32+n], y);
            }
            y_ptr[t*D_] = fmaf(xv + xr, dsk, y);
        }
    }
}

// ---------------------------------------------------------------------------
// Kernel 5: out = y @ W_out^T (unchanged fp32 SIMT GEMM).
// ---------------------------------------------------------------------------
__global__ __launch_bounds__(256) void gemm_kernel(
    float* __restrict__ out, const float* __restrict__ Wout)
{
    __shared__ float As[16][128];
    __shared__ float Bs[16][64];

    const int j0 = blockIdx.x * 64;
    const int m0 = blockIdx.y * 128;
    const int tid = threadIdx.x;
    const int tx = tid & 15;
    const int ty = tid >> 4;

    float acc[8][4];
    #pragma unroll
    for (int i = 0; i < 8; ++i)
        #pragma unroll
        for (int u = 0; u < 4; ++u) acc[i][u] = 0.f;

    const int arow0 = tid >> 2, ac4 = tid & 3;
    const int brow = tid >> 2, bc4 = tid & 3;

    for (int k0 = 0; k0 < 256; k0 += 16) {
        #pragma unroll
        for (int it = 0; it < 2; ++it) {
            const int row = arow0 + it*64;
            const float4 v = *reinterpret_cast<const float4*>(
                g_y + (m0 + row)*D_ + k0 + ac4*4);
            As[ac4*4 + 0][row] = v.x;
            As[ac4*4 + 1][row] = v.y;
            As[ac4*4 + 2][row] = v.z;
            As[ac4*4 + 3][row] = v.w;
        }
        {
            const float4 v = *reinterpret_cast<const float4*>(
                Wout + (j0 + brow)*D_ + k0 + bc4*4);
            Bs[bc4*4 + 0][brow] = v.x;
            Bs[bc4*4 + 1][brow] = v.y;
            Bs[bc4*4 + 2][brow] = v.z;
            Bs[bc4*4 + 3][brow] = v.w;
        }
        __syncthreads();

        #pragma unroll
        for (int kk = 0; kk < 16; ++kk) {
            const float4 a0 = *reinterpret_cast<const float4*>(&As[kk][ty*8]);
            const float4 a1 = *reinterpret_cast<const float4*>(&As[kk][ty*8 + 4]);
            const float4 b  = *reinterpret_cast<const float4*>(&Bs[kk][tx*4]);
            const float am[8] = {a0.x,a0.y,a0.z,a0.w,a1.x,a1.y,a1.z,a1.w};
            const float bm[4] = {b.x,b.y,b.z,b.w};
            #pragma unroll
            for (int i = 0; i < 8; ++i)
                #pragma unroll
                for (int u = 0; u < 4; ++u)
                    acc[i][u] = fmaf(am[i], bm[u], acc[i][u]);
        }
        __syncthreads();
    }

    #pragma unroll
    for (int i = 0; i < 8; ++i) {
        float4 v = make_float4(acc[i][0], acc[i][1], acc[i][2], acc[i][3]);
        *reinterpret_cast<float4*>(out + (m0 + ty*8 + i)*D_ + j0 + tx*4) = v;
    }
}

// ---------------------------------------------------------------------------
extern "C" void kernel_launch(void* const* d_in, const int* in_sizes, int n_in,
                              void* d_out, int out_size)
{
    const float* x     = (const float*)d_in[0];
    const float* Wxp   = (const float*)d_in[1];
    const float* Wxb   = (const float*)d_in[2];
    const float* Wdt   = (const float*)d_in[3];
    const float* bdt   = (const float*)d_in[4];
    const float* A_log = (const float*)d_in[5];
    const float* Dskip = (const float*)d_in[6];
    const float* Wout  = (const float*)d_in[7];
    float* out = (float*)d_out;

    proj_kernel   <<<(B_*L_)/16, 256>>>(x, Wxp, Wxb, Wdt, bdt);
    scan1_kernel  <<<B_*NC,      256>>>(x, A_log);
    combine_kernel<<<(B_*N_*D_)/256, 256>>>();
    scan2_kernel  <<<B_*NC,      256>>>(x, A_log, Dskip);
    gemm_kernel   <<<dim3(4, 128), 256>>>(out, Wout);
}

// round 4
// speedup vs baseline: 1.2154x; 1.0935x over previous
#include <cuda_runtime.h>
#include <math.h>

#define B_    8
#define L_    2048
#define D_    256
#define N_    16
#define R_    16
#define NPROJ 80
#define CL    32          // scan chunk length
#define NC    (L_/CL)     // 64 chunks

// ---------------- scratch (device globals) ----------------
__device__ float g_delta  [B_*L_*D_];
__device__ float g_delta_b[B_*L_*D_];
__device__ float g_BC     [B_*L_*48];      // Bf(16) Bb(16) C(16)
__device__ float g_pc     [B_*L_*D_];      // cumulative p1 within chunk (fast path)
__device__ float g_P      [B_*NC*N_*D_];
__device__ float g_H      [B_*NC*N_*D_];
__device__ float g_hs     [B_*NC*N_*D_];
__device__ float g_y      [B_*L_*D_];

__device__ __forceinline__ float softplusf(float v) {
    return v > 20.0f ? v : log1pf(__expf(v));
}

__device__ __forceinline__ void powers16(float p1, float e[N_]) {
    e[0]  = p1;
    e[1]  = p1 * p1;
    e[2]  = e[1] * p1;
    e[3]  = e[1] * e[1];
    e[4]  = e[3] * p1;
    e[5]  = e[3] * e[1];
    e[6]  = e[3] * e[2];
    e[7]  = e[3] * e[3];
    e[8]  = e[7] * p1;
    e[9]  = e[7] * e[1];
    e[10] = e[7] * e[2];
    e[11] = e[7] * e[3];
    e[12] = e[7] * e[4];
    e[13] = e[7] * e[5];
    e[14] = e[7] * e[6];
    e[15] = e[7] * e[7];
}

__device__ __forceinline__ float check_A(const float* __restrict__ A_log,
                                         int d, bool& fast) {
    float a0 = -__expf(__ldg(A_log + d*N_));
    fast = true;
    #pragma unroll
    for (int n = 1; n < N_; ++n) {
        float an = -__expf(__ldg(A_log + d*N_ + n));
        fast = fast && (fabsf(an - a0*(float)(n+1)) <= 1e-4f*(float)(n+1));
    }
    return a0;
}

// ---------------------------------------------------------------------------
// Kernel 1: fused projections (unchanged).
// ---------------------------------------------------------------------------
__global__ __launch_bounds__(256) void proj_kernel(
    const float* __restrict__ x, const float* __restrict__ Wxp,
    const float* __restrict__ Wxb, const float* __restrict__ Wdt,
    const float* __restrict__ bdt)
{
    const int ROWS = 16;
    __shared__ float sx[ROWS][D_];
    __shared__ float sp[ROWS][NPROJ];
    __shared__ float sWdtT[R_][D_];

    const int row0 = blockIdx.x * ROWS;
    const int tid  = threadIdx.x;

    for (int i = tid; i < D_*R_; i += 256) {
        int d = i / R_, r = i % R_;
        sWdtT[r][d] = Wdt[i];
    }
    for (int i = tid; i < ROWS*D_; i += 256)
        sx[i >> 8][i & 255] = x[row0*D_ + i];
    __syncthreads();

    const int warp = tid >> 5, lane = tid & 31;
    #pragma unroll
    for (int t = 0; t < 10; ++t) {
        int j = warp + 8*t;
        const float* Wrow = (j < 64) ? (Wxp + j*D_) : (Wxb + (j-64)*D_);
        float wv[8];
        #pragma unroll
        for (int k = 0; k < 8; ++k) wv[k] = __ldg(Wrow + lane + 32*k);
        for (int r = 0; r < ROWS; ++r) {
            float acc = 0.f;
            #pragma unroll
            for (int k = 0; k < 8; ++k) acc = fmaf(wv[k], sx[r][lane + 32*k], acc);
            #pragma unroll
            for (int o = 16; o; o >>= 1) acc += __shfl_xor_sync(0xffffffffu, acc, o);
            if (lane == 0) sp[r][j] = acc;
        }
    }
    __syncthreads();

    for (int i = tid; i < ROWS*48; i += 256) {
        int r = i / 48, c = i - r*48;
        g_BC[(row0 + r)*48 + c] = sp[r][16 + c];
    }

    float wdt[R_];
    #pragma unroll
    for (int q = 0; q < R_; ++q) wdt[q] = sWdtT[q][tid];
    const float bv = bdt[tid];

    for (int r = 0; r < ROWS; ++r) {
        float s = bv, sb = bv;
        #pragma unroll
        for (int q = 0; q < R_; ++q) {
            s  = fmaf(sp[r][q],      wdt[q], s);
            sb = fmaf(sp[r][64 + q], wdt[q], sb);
        }
        const int m = row0 + r;
        const int b = m >> 11;
        const int l = m & (L_ - 1);
        g_delta[m*D_ + tid]                              = softplusf(s);
        g_delta_b[((b << 11) + (L_ - 1 - l))*D_ + tid]   = softplusf(sb);
    }
}

// ---------------------------------------------------------------------------
// Kernel 2: scan_local — local recurrence from h=0; emits
//   y_local (incl. skip term), p1cum per step (fast path),
//   chunk decay P and local end state H.
// ---------------------------------------------------------------------------
__global__ __launch_bounds__(256) void scan_local_kernel(
    const float* __restrict__ x, const float* __restrict__ A_log,
    const float* __restrict__ Dskip)
{
    const int bc = blockIdx.x;
    const int b = bc / NC, c = bc - b*NC;
    const int d = threadIdx.x;
    const int l0 = c * CL;

    __shared__ float sB[CL][48];
    for (int i = d; i < CL*48; i += 256) {
        int t = i / 48, j = i - t*48;
        sB[t][j] = g_BC[(b*L_ + l0 + t)*48 + j];
    }
    __syncthreads();

    bool fast;
    const float a0 = check_A(A_log, d, fast);
    const float dsk = Dskip[d];

    float h[N_];
    #pragma unroll
    for (int n = 0; n < N_; ++n) h[n] = 0.f;

    const float* dl_ptr  = g_delta   + (b*L_ + l0)*D_ + d;
    const float* dlb_ptr = g_delta_b + (b*L_ + l0)*D_ + d;
    const float* x_ptr   = x + (b*L_ + l0)*D_ + d;
    const float* xr_ptr  = x + (b*L_ + (L_ - 1 - l0))*D_ + d;
    float* y_ptr  = g_y  + (b*L_ + l0)*D_ + d;
    float* pc_ptr = g_pc + (b*L_ + l0)*D_ + d;

    float* Pp = g_P + ((b*NC + c)*N_)*D_ + d;
    float* Hp = g_H + ((b*NC + c)*N_)*D_ + d;

    if (fast) {
        float p1 = 1.f;
        #pragma unroll
        for (int t0 = 0; t0 < CL; t0 += 4) {
            float dl[4], dlb[4], xv[4], xr[4];
            #pragma unroll
            for (int i = 0; i < 4; ++i) {
                dl[i]  = dl_ptr [(t0+i)*D_];
                dlb[i] = dlb_ptr[(t0+i)*D_];
                xv[i]  = x_ptr  [(t0+i)*D_];
                xr[i]  = xr_ptr [-(t0+i)*D_];
            }
            #pragma unroll
            for (int i = 0; i < 4; ++i) {
                const int t = t0 + i;
                const float e1 = __expf(dl[i] * a0);
                float e[N_]; powers16(e1, e);
                const float c1 = dl[i]*xv[i], c2 = dlb[i]*xr[i];
                float y = 0.f;
                #pragma unroll
                for (int n = 0; n < N_; ++n) {
                    h[n] = fmaf(e[n], h[n], fmaf(c1, sB[t][n], c2 * sB[t][16+n]));
                    y    = fmaf(h[n], sB[t][32+n], y);
                }
                p1 *= e1;
                y_ptr [t*D_] = fmaf(xv[i] + xr[i], dsk, y);
                pc_ptr[t*D_] = p1;
            }
        }
        float pw[N_]; powers16(p1, pw);
        #pragma unroll
        for (int n = 0; n < N_; ++n) { Pp[n*D_] = pw[n]; Hp[n*D_] = h[n]; }
    } else {
        float a[N_], p[N_];
        #pragma unroll
        for (int n = 0; n < N_; ++n) {
            a[n] = -__expf(__ldg(A_log + d*N_ + n));
            p[n] = 1.f;
        }
        for (int t = 0; t < CL; ++t) {
            const float dl  = dl_ptr[t*D_];
            const float dlb = dlb_ptr[t*D_];
            const float xv  = x_ptr[t*D_];
            const float xr  = xr_ptr[-t*D_];
            const float c1 = dl*xv, c2 = dlb*xr;
            float y = 0.f;
            #pragma unroll
            for (int n = 0; n < N_; ++n) {
                const float e = __expf(dl * a[n]);
                h[n] = fmaf(e, h[n], fmaf(c1, sB[t][n], c2 * sB[t][16+n]));
                y    = fmaf(h[n], sB[t][32+n], y);
                p[n] *= e;
            }
            y_ptr[t*D_] = fmaf(xv + xr, dsk, y);
        }
        #pragma unroll
        for (int n = 0; n < N_; ++n) { Pp[n*D_] = p[n]; Hp[n*D_] = h[n]; }
    }
}

// ---------------------------------------------------------------------------
// Kernel 3: sequential combine across chunks, with batched loads for MLP.
// ---------------------------------------------------------------------------
__global__ __launch_bounds__(256) void combine_kernel()
{
    const int idx = blockIdx.x*256 + threadIdx.x;   // B_*N_*D_ = 32768
    const int d = idx & (D_ - 1);
    const int n = (idx >> 8) & (N_ - 1);
    const int b = idx >> 12;
    const int base = (b*NC*N_ + n)*D_ + d;
    const int stride = N_*D_;

    float hs = 0.f;
    #pragma unroll 1
    for (int c0 = 0; c0 < NC; c0 += 8) {
        float pv[8], hv[8];
        #pragma unroll
        for (int i = 0; i < 8; ++i) {
            pv[i] = g_P[base + (c0+i)*stride];
            hv[i] = g_H[base + (c0+i)*stride];
        }
        #pragma unroll
        for (int i = 0; i < 8; ++i) {
            g_hs[base + (c0+i)*stride] = hs;
            hs = fmaf(pv[i], hs, hv[i]);
        }
    }
}

// ---------------------------------------------------------------------------
// Kernel 4: correct2 — y[t] += sum_n pcum_t[n] * h_start[n] * C[t][n].
// Fast path: pcum from stored scalar p1cum via power tree (no exp, no chain).
// Slow path: recompute decays with exps (running product).
// ---------------------------------------------------------------------------
__global__ __launch_bounds__(256) void correct2_kernel(
    const float* __restrict__ A_log)
{
    const int bc = blockIdx.x;
    const int b = bc / NC, c = bc - b*NC;
    const int d = threadIdx.x;
    const int l0 = c * CL;

    __shared__ float sC[CL][N_];   // C only (2 KB)
    for (int i = d; i < CL*N_; i += 256) {
        int t = i >> 4, j = i & 15;
        sC[t][j] = g_BC[(b*L_ + l0 + t)*48 + 32 + j];
    }
    __syncthreads();

    bool fast;
    const float a0 = check_A(A_log, d, fast);
    (void)a0;

    float q[N_];   // h_start (fast) / running pcum*h_start (slow)
    #pragma unroll
    for (int n = 0; n < N_; ++n)
        q[n] = g_hs[((b*NC + c)*N_ + n)*D_ + d];

    float* y_ptr        = g_y  + (b*L_ + l0)*D_ + d;
    const float* pc_ptr = g_pc + (b*L_ + l0)*D_ + d;

    if (fast) {
        #pragma unroll
        for (int t0 = 0; t0 < CL; t0 += 4) {
            float p1[4], yl[4];
            #pragma unroll
            for (int i = 0; i < 4; ++i) {
                p1[i] = pc_ptr[(t0+i)*D_];
                yl[i] = y_ptr [(t0+i)*D_];
            }
            #pragma unroll
            for (int i = 0; i < 4; ++i) {
                const int t = t0 + i;
                float pw[N_]; powers16(p1[i], pw);
                float corr = 0.f;
                #pragma unroll
                for (int n = 0; n < N_; ++n)
                    corr = fmaf(pw[n] * q[n], sC[t][n], corr);
                y_ptr[t*D_] = yl[i] + corr;
            }
        }
    } else {
        const float* dl_ptr = g_delta + (b*L_ + l0)*D_ + d;
        float a[N_];
        #pragma unroll
        for (int n = 0; n < N_; ++n)
            a[n] = -__expf(__ldg(A_log + d*N_ + n));
        for (int t = 0; t < CL; ++t) {
            const float dl = dl_ptr[t*D_];
            float corr = 0.f;
            #pragma unroll
            for (int n = 0; n < N_; ++n) {
                q[n] *= __expf(dl * a[n]);
                corr = fmaf(q[n], sC[t][n], corr);
            }
            y_ptr[t*D_] += corr;
        }
    }
}

// ---------------------------------------------------------------------------
// Kernel 5: out = y @ W_out^T (unchanged fp32 SIMT GEMM).
// ---------------------------------------------------------------------------
__global__ __launch_bounds__(256) void gemm_kernel(
    float* __restrict__ out, const float* __restrict__ Wout)
{
    __shared__ float As[16][128];
    __shared__ float Bs[16][64];

    const int j0 = blockIdx.x * 64;
    const int m0 = blockIdx.y * 128;
    const int tid = threadIdx.x;
    const int tx = tid & 15;
    const int ty = tid >> 4;

    float acc[8][4];
    #pragma unroll
    for (int i = 0; i < 8; ++i)
        #pragma unroll
        for (int u = 0; u < 4; ++u) acc[i][u] = 0.f;

    const int arow0 = tid >> 2, ac4 = tid & 3;
    const int brow = tid >> 2, bc4 = tid & 3;

    for (int k0 = 0; k0 < 256; k0 += 16) {
        #pragma unroll
        for (int it = 0; it < 2; ++it) {
            const int row = arow0 + it*64;
            const float4 v = *reinterpret_cast<const float4*>(
                g_y + (m0 + row)*D_ + k0 + ac4*4);
            As[ac4*4 + 0][row] = v.x;
            As[ac4*4 + 1][row] = v.y;
            As[ac4*4 + 2][row] = v.z;
            As[ac4*4 + 3][row] = v.w;
        }
        {
            const float4 v = *reinterpret_cast<const float4*>(
                Wout + (j0 + brow)*D_ + k0 + bc4*4);
            Bs[bc4*4 + 0][brow] = v.x;
            Bs[bc4*4 + 1][brow] = v.y;
            Bs[bc4*4 + 2][brow] = v.z;
            Bs[bc4*4 + 3][brow] = v.w;
        }
        __syncthreads();

        #pragma unroll
        for (int kk = 0; kk < 16; ++kk) {
            const float4 a0 = *reinterpret_cast<const float4*>(&As[kk][ty*8]);
            const float4 a1 = *reinterpret_cast<const float4*>(&As[kk][ty*8 + 4]);
            const float4 b  = *reinterpret_cast<const float4*>(&Bs[kk][tx*4]);
            const float am[8] = {a0.x,a0.y,a0.z,a0.w,a1.x,a1.y,a1.z,a1.w};
            const float bm[4] = {b.x,b.y,b.z,b.w};
            #pragma unroll
            for (int i = 0; i < 8; ++i)
                #pragma unroll
                for (int u = 0; u < 4; ++u)
                    acc[i][u] = fmaf(am[i], bm[u], acc[i][u]);
        }
        __syncthreads();
    }

    #pragma unroll
    for (int i = 0; i < 8; ++i) {
        float4 v = make_float4(acc[i][0], acc[i][1], acc[i][2], acc[i][3]);
        *reinterpret_cast<float4*>(out + (m0 + ty*8 + i)*D_ + j0 + tx*4) = v;
    }
}

// ---------------------------------------------------------------------------
extern "C" void kernel_launch(void* const* d_in, const int* in_sizes, int n_in,
                              void* d_out, int out_size)
{
    const float* x     = (const float*)d_in[0];
    const float* Wxp   = (const float*)d_in[1];
    const float* Wxb   = (const float*)d_in[2];
    const float* Wdt   = (const float*)d_in[3];
    const float* bdt   = (const float*)d_in[4];
    const float* A_log = (const float*)d_in[5];
    const float* Dskip = (const float*)d_in[6];
    const float* Wout  = (const float*)d_in[7];
    float* out = (float*)d_out;

    proj_kernel      <<<(B_*L_)/16, 256>>>(x, Wxp, Wxb, Wdt, bdt);
    scan_local_kernel<<<B_*NC,      256>>>(x, A_log, Dskip);
    combine_kernel   <<<(B_*N_*D_)/256, 256>>>();
    correct2_kernel  <<<B_*NC,      256>>>(A_log);
    gemm_kernel      <<<dim3(4, 128), 256>>>(out, Wout);
}

// round 6
// speedup vs baseline: 1.4791x; 1.2170x over previous
#include <cuda_runtime.h>
#include <cuda_bf16.h>
#include <math.h>
#include <stdint.h>

#define B_    8
#define L_    2048
#define D_    256
#define N_    16
#define R_    16
#define NPROJ 80
#define CL    32          // scan chunk length
#define NC    (L_/CL)     // 64 chunks

// ---------------- scratch (device globals) ----------------
__device__ float g_delta  [B_*L_*D_];
__device__ float g_delta_b[B_*L_*D_];
__device__ float g_BC     [B_*L_*48];      // Bf(16) Bb(16) C(16)
__device__ float g_pc     [B_*L_*D_];      // cumulative p1 within chunk (fast path)
__device__ float g_P      [B_*NC*N_*D_];
__device__ float g_H      [B_*NC*N_*D_];
__device__ float g_hs     [B_*NC*N_*D_];
__device__ float g_y      [B_*L_*D_];

__device__ __forceinline__ float softplusf(float v) {
    return v > 20.0f ? v : log1pf(__expf(v));
}

__device__ __forceinline__ void powers16(float p1, float e[N_]) {
    e[0]  = p1;
    e[1]  = p1 * p1;
    e[2]  = e[1] * p1;
    e[3]  = e[1] * e[1];
    e[4]  = e[3] * p1;
    e[5]  = e[3] * e[1];
    e[6]  = e[3] * e[2];
    e[7]  = e[3] * e[3];
    e[8]  = e[7] * p1;
    e[9]  = e[7] * e[1];
    e[10] = e[7] * e[2];
    e[11] = e[7] * e[3];
    e[12] = e[7] * e[4];
    e[13] = e[7] * e[5];
    e[14] = e[7] * e[6];
    e[15] = e[7] * e[7];
}

__device__ __forceinline__ float check_A(const float* __restrict__ A_log,
                                         int d, bool& fast) {
    float a0 = -__expf(__ldg(A_log + d*N_));
    fast = true;
    #pragma unroll
    for (int n = 1; n < N_; ++n) {
        float an = -__expf(__ldg(A_log + d*N_ + n));
        fast = fast && (fabsf(an - a0*(float)(n+1)) <= 1e-4f*(float)(n+1));
    }
    return a0;
}

// ---------------------------------------------------------------------------
// Kernel 1: fused projections (unchanged).
// ---------------------------------------------------------------------------
__global__ __launch_bounds__(256) void proj_kernel(
    const float* __restrict__ x, const float* __restrict__ Wxp,
    const float* __restrict__ Wxb, const float* __restrict__ Wdt,
    const float* __restrict__ bdt)
{
    const int ROWS = 16;
    __shared__ float sx[ROWS][D_];
    __shared__ float sp[ROWS][NPROJ];
    __shared__ float sWdtT[R_][D_];

    const int row0 = blockIdx.x * ROWS;
    const int tid  = threadIdx.x;

    for (int i = tid; i < D_*R_; i += 256) {
        int d = i / R_, r = i % R_;
        sWdtT[r][d] = Wdt[i];
    }
    for (int i = tid; i < ROWS*D_; i += 256)
        sx[i >> 8][i & 255] = x[row0*D_ + i];
    __syncthreads();

    const int warp = tid >> 5, lane = tid & 31;
    #pragma unroll
    for (int t = 0; t < 10; ++t) {
        int j = warp + 8*t;
        const float* Wrow = (j < 64) ? (Wxp + j*D_) : (Wxb + (j-64)*D_);
        float wv[8];
        #pragma unroll
        for (int k = 0; k < 8; ++k) wv[k] = __ldg(Wrow + lane + 32*k);
        for (int r = 0; r < ROWS; ++r) {
            float acc = 0.f;
            #pragma unroll
            for (int k = 0; k < 8; ++k) acc = fmaf(wv[k], sx[r][lane + 32*k], acc);
            #pragma unroll
            for (int o = 16; o; o >>= 1) acc += __shfl_xor_sync(0xffffffffu, acc, o);
            if (lane == 0) sp[r][j] = acc;
        }
    }
    __syncthreads();

    for (int i = tid; i < ROWS*48; i += 256) {
        int r = i / 48, c = i - r*48;
        g_BC[(row0 + r)*48 + c] = sp[r][16 + c];
    }

    float wdt[R_];
    #pragma unroll
    for (int q = 0; q < R_; ++q) wdt[q] = sWdtT[q][tid];
    const float bv = bdt[tid];

    for (int r = 0; r < ROWS; ++r) {
        float s = bv, sb = bv;
        #pragma unroll
        for (int q = 0; q < R_; ++q) {
            s  = fmaf(sp[r][q],      wdt[q], s);
            sb = fmaf(sp[r][64 + q], wdt[q], sb);
        }
        const int m = row0 + r;
        const int b = m >> 11;
        const int l = m & (L_ - 1);
        g_delta[m*D_ + tid]                              = softplusf(s);
        g_delta_b[((b << 11) + (L_ - 1 - l))*D_ + tid]   = softplusf(sb);
    }
}

// ---------------------------------------------------------------------------
// Kernel 2: scan_local (unchanged).
// ---------------------------------------------------------------------------
__global__ __launch_bounds__(256) void scan_local_kernel(
    const float* __restrict__ x, const float* __restrict__ A_log,
    const float* __restrict__ Dskip)
{
    const int bc = blockIdx.x;
    const int b = bc / NC, c = bc - b*NC;
    const int d = threadIdx.x;
    const int l0 = c * CL;

    __shared__ float sB[CL][48];
    for (int i = d; i < CL*48; i += 256) {
        int t = i / 48, j = i - t*48;
        sB[t][j] = g_BC[(b*L_ + l0 + t)*48 + j];
    }
    __syncthreads();

    bool fast;
    const float a0 = check_A(A_log, d, fast);
    const float dsk = Dskip[d];

    float h[N_];
    #pragma unroll
    for (int n = 0; n < N_; ++n) h[n] = 0.f;

    const float* dl_ptr  = g_delta   + (b*L_ + l0)*D_ + d;
    const float* dlb_ptr = g_delta_b + (b*L_ + l0)*D_ + d;
    const float* x_ptr   = x + (b*L_ + l0)*D_ + d;
    const float* xr_ptr  = x + (b*L_ + (L_ - 1 - l0))*D_ + d;
    float* y_ptr  = g_y  + (b*L_ + l0)*D_ + d;
    float* pc_ptr = g_pc + (b*L_ + l0)*D_ + d;

    float* Pp = g_P + ((b*NC + c)*N_)*D_ + d;
    float* Hp = g_H + ((b*NC + c)*N_)*D_ + d;

    if (fast) {
        float p1 = 1.f;
        #pragma unroll
        for (int t0 = 0; t0 < CL; t0 += 4) {
            float dl[4], dlb[4], xv[4], xr[4];
            #pragma unroll
            for (int i = 0; i < 4; ++i) {
                dl[i]  = dl_ptr [(t0+i)*D_];
                dlb[i] = dlb_ptr[(t0+i)*D_];
                xv[i]  = x_ptr  [(t0+i)*D_];
                xr[i]  = xr_ptr [-(t0+i)*D_];
            }
            #pragma unroll
            for (int i = 0; i < 4; ++i) {
                const int t = t0 + i;
                const float e1 = __expf(dl[i] * a0);
                float e[N_]; powers16(e1, e);
                const float c1 = dl[i]*xv[i], c2 = dlb[i]*xr[i];
                float y = 0.f;
                #pragma unroll
                for (int n = 0; n < N_; ++n) {
                    h[n] = fmaf(e[n], h[n], fmaf(c1, sB[t][n], c2 * sB[t][16+n]));
                    y    = fmaf(h[n], sB[t][32+n], y);
                }
                p1 *= e1;
                y_ptr [t*D_] = fmaf(xv[i] + xr[i], dsk, y);
                pc_ptr[t*D_] = p1;
            }
        }
        float pw[N_]; powers16(p1, pw);
        #pragma unroll
        for (int n = 0; n < N_; ++n) { Pp[n*D_] = pw[n]; Hp[n*D_] = h[n]; }
    } else {
        float a[N_], p[N_];
        #pragma unroll
        for (int n = 0; n < N_; ++n) {
            a[n] = -__expf(__ldg(A_log + d*N_ + n));
            p[n] = 1.f;
        }
        for (int t = 0; t < CL; ++t) {
            const float dl  = dl_ptr[t*D_];
            const float dlb = dlb_ptr[t*D_];
            const float xv  = x_ptr[t*D_];
            const float xr  = xr_ptr[-t*D_];
            const float c1 = dl*xv, c2 = dlb*xr;
            float y = 0.f;
            #pragma unroll
            for (int n = 0; n < N_; ++n) {
                const float e = __expf(dl * a[n]);
                h[n] = fmaf(e, h[n], fmaf(c1, sB[t][n], c2 * sB[t][16+n]));
                y    = fmaf(h[n], sB[t][32+n], y);
                p[n] *= e;
            }
            y_ptr[t*D_] = fmaf(xv + xr, dsk, y);
        }
        #pragma unroll
        for (int n = 0; n < N_; ++n) { Pp[n*D_] = p[n]; Hp[n*D_] = h[n]; }
    }
}

// ---------------------------------------------------------------------------
// Kernel 3: sequential combine across chunks (unchanged).
// ---------------------------------------------------------------------------
__global__ __launch_bounds__(256) void combine_kernel()
{
    const int idx = blockIdx.x*256 + threadIdx.x;
    const int d = idx & (D_ - 1);
    const int n = (idx >> 8) & (N_ - 1);
    const int b = idx >> 12;
    const int base = (b*NC*N_ + n)*D_ + d;
    const int stride = N_*D_;

    float hs = 0.f;
    #pragma unroll 1
    for (int c0 = 0; c0 < NC; c0 += 8) {
        float pv[8], hv[8];
        #pragma unroll
        for (int i = 0; i < 8; ++i) {
            pv[i] = g_P[base + (c0+i)*stride];
            hv[i] = g_H[base + (c0+i)*stride];
        }
        #pragma unroll
        for (int i = 0; i < 8; ++i) {
            g_hs[base + (c0+i)*stride] = hs;
            hs = fmaf(pv[i], hs, hv[i]);
        }
    }
}

// ---------------------------------------------------------------------------
// Kernel 4: correct2 (unchanged).
// ---------------------------------------------------------------------------
__global__ __launch_bounds__(256) void correct2_kernel(
    const float* __restrict__ A_log)
{
    const int bc = blockIdx.x;
    const int b = bc / NC, c = bc - b*NC;
    const int d = threadIdx.x;
    const int l0 = c * CL;

    __shared__ float sC[CL][N_];
    for (int i = d; i < CL*N_; i += 256) {
        int t = i >> 4, j = i & 15;
        sC[t][j] = g_BC[(b*L_ + l0 + t)*48 + 32 + j];
    }
    __syncthreads();

    bool fast;
    const float a0 = check_A(A_log, d, fast);
    (void)a0;

    float q[N_];
    #pragma unroll
    for (int n = 0; n < N_; ++n)
        q[n] = g_hs[((b*NC + c)*N_ + n)*D_ + d];

    float* y_ptr        = g_y  + (b*L_ + l0)*D_ + d;
    const float* pc_ptr = g_pc + (b*L_ + l0)*D_ + d;

    if (fast) {
        #pragma unroll
        for (int t0 = 0; t0 < CL; t0 += 4) {
            float p1[4], yl[4];
            #pragma unroll
            for (int i = 0; i < 4; ++i) {
                p1[i] = pc_ptr[(t0+i)*D_];
                yl[i] = y_ptr [(t0+i)*D_];
            }
            #pragma unroll
            for (int i = 0; i < 4; ++i) {
                const int t = t0 + i;
                float pw[N_]; powers16(p1[i], pw);
                float corr = 0.f;
                #pragma unroll
                for (int n = 0; n < N_; ++n)
                    corr = fmaf(pw[n] * q[n], sC[t][n], corr);
                y_ptr[t*D_] = yl[i] + corr;
            }
        }
    } else {
        const float* dl_ptr = g_delta + (b*L_ + l0)*D_ + d;
        float a[N_];
        #pragma unroll
        for (int n = 0; n < N_; ++n)
            a[n] = -__expf(__ldg(A_log + d*N_ + n));
        for (int t = 0; t < CL; ++t) {
            const float dl = dl_ptr[t*D_];
            float corr = 0.f;
            #pragma unroll
            for (int n = 0; n < N_; ++n) {
                q[n] *= __expf(dl * a[n]);
                corr = fmaf(q[n], sC[t][n], corr);
            }
            y_ptr[t*D_] += corr;
        }
    }
}

// ---------------------------------------------------------------------------
// Kernel 5: out = y @ W_out^T via mma.sync bf16 split (3 terms, fp32 accum).
// CTA tile 128x128; 8 warps (2m x 4n), warp tile 64x32 = 4x4 m16n8k16 frags.
// Fragments loaded as contiguous bf16x2 pairs (no ldmatrix needed for
// row.col layout). Smem row pitch 72 bf16 (36 words = 4 mod 32 banks).
// ---------------------------------------------------------------------------
#define GP 72   // smem pitch in bf16 elements

__device__ __forceinline__ void mma_bf16(float d[4],
                                         const uint32_t a[4],
                                         const uint32_t b[2]) {
    asm volatile(
        "mma.sync.aligned.m16n8k16.row.col.f32.bf16.bf16.f32 "
        "{%0,%1,%2,%3}, {%4,%5,%6,%7}, {%8,%9}, {%0,%1,%2,%3};"
        : "+f"(d[0]), "+f"(d[1]), "+f"(d[2]), "+f"(d[3])
        : "r"(a[0]), "r"(a[1]), "r"(a[2]), "r"(a[3]), "r"(b[0]), "r"(b[1]));
}

__global__ __launch_bounds__(256) void gemm_mma_kernel(
    float* __restrict__ out, const float* __restrict__ Wout)
{
    extern __shared__ __nv_bfloat16 sm[];
    __nv_bfloat16* sA_hi = sm;                 // [128][GP]
    __nv_bfloat16* sA_lo = sm + 128*GP;
    __nv_bfloat16* sB_hi = sm + 2*128*GP;
    __nv_bfloat16* sB_lo = sm + 3*128*GP;

    const int tid  = threadIdx.x;
    const int wid  = tid >> 5;
    const int lane = tid & 31;
    const int gid  = lane >> 2;      // group id 0..7
    const int t4   = lane & 3;       // thread-in-group 0..3

    const int j0 = blockIdx.x * 128; // N tile
    const int m0 = blockIdx.y * 128; // M tile
    const int wm = (wid >> 2) * 64;  // warp m offset in tile
    const int wn = (wid & 3) * 32;   // warp n offset in tile

    float acc[4][4][4];
    #pragma unroll
    for (int i = 0; i < 4; ++i)
        #pragma unroll
        for (int j = 0; j < 4; ++j)
            #pragma unroll
            for (int q = 0; q < 4; ++q) acc[i][j][q] = 0.f;

    const int lrow = tid >> 5;       // load: 8 rows per pass, 32 pairs/row
    const int lpc  = tid & 31;       // pair column

    for (int kc = 0; kc < 256; kc += 64) {
        __syncthreads();   // protect smem reuse from previous chunk
        // Fill A/B hi-lo tiles: 128 rows x 32 bf16x2 pairs each.
        #pragma unroll
        for (int rr = 0; rr < 16; ++rr) {
            const int row = lrow + rr*8;
            const int soff = row*GP + lpc*2;

            const float2 va = *reinterpret_cast<const float2*>(
                g_y + (m0 + row)*D_ + kc + lpc*2);
            __nv_bfloat16 ahx = __float2bfloat16(va.x);
            __nv_bfloat16 ahy = __float2bfloat16(va.y);
            __nv_bfloat16 alx = __float2bfloat16(va.x - __bfloat162float(ahx));
            __nv_bfloat16 aly = __float2bfloat16(va.y - __bfloat162float(ahy));
            *reinterpret_cast<__nv_bfloat162*>(sA_hi + soff) = __nv_bfloat162(ahx, ahy);
            *reinterpret_cast<__nv_bfloat162*>(sA_lo + soff) = __nv_bfloat162(alx, aly);

            const float2 vb = *reinterpret_cast<const float2*>(
                Wout + (j0 + row)*D_ + kc + lpc*2);
            __nv_bfloat16 bhx = __float2bfloat16(vb.x);
            __nv_bfloat16 bhy = __float2bfloat16(vb.y);
            __nv_bfloat16 blx = __float2bfloat16(vb.x - __bfloat162float(bhx));
            __nv_bfloat16 bly = __float2bfloat16(vb.y - __bfloat162float(bhy));
            *reinterpret_cast<__nv_bfloat162*>(sB_hi + soff) = __nv_bfloat162(bhx, bhy);
            *reinterpret_cast<__nv_bfloat162*>(sB_lo + soff) = __nv_bfloat162(blx, bly);
        }
        __syncthreads();

        #pragma unroll
        for (int ks = 0; ks < 4; ++ks) {
            const int k0 = ks*16;
            uint32_t a_hi[4][4], a_lo[4][4], b_hi[4][2], b_lo[4][2];

            #pragma unroll
            for (int mf = 0; mf < 4; ++mf) {
                const int r0 = wm + mf*16 + gid;
                const int c0 = k0 + t4*2;
                a_hi[mf][0] = *reinterpret_cast<const uint32_t*>(sA_hi + (r0    )*GP + c0    );
                a_hi[mf][1] = *reinterpret_cast<const uint32_t*>(sA_hi + (r0 + 8)*GP + c0    );
                a_hi[mf][2] = *reinterpret_cast<const uint32_t*>(sA_hi + (r0    )*GP + c0 + 8);
                a_hi[mf][3] = *reinterpret_cast<const uint32_t*>(sA_hi + (r0 + 8)*GP + c0 + 8);
                a_lo[mf][0] = *reinterpret_cast<const uint32_t*>(sA_lo + (r0    )*GP + c0    );
                a_lo[mf][1] = *reinterpret_cast<const uint32_t*>(sA_lo + (r0 + 8)*GP + c0    );
                a_lo[mf][2] = *reinterpret_cast<const uint32_t*>(sA_lo + (r0    )*GP + c0 + 8);
                a_lo[mf][3] = *reinterpret_cast<const uint32_t*>(sA_lo + (r0 + 8)*GP + c0 + 8);
            }
            #pragma unroll
            for (int nf = 0; nf < 4; ++nf) {
                const int nr = wn + nf*8 + gid;
                const int c0 = k0 + t4*2;
                b_hi[nf][0] = *reinterpret_cast<const uint32_t*>(sB_hi + nr*GP + c0    );
                b_hi[nf][1] = *reinterpret_cast<const uint32_t*>(sB_hi + nr*GP + c0 + 8);
                b_lo[nf][0] = *reinterpret_cast<const uint32_t*>(sB_lo + nr*GP + c0    );
                b_lo[nf][1] = *reinterpret_cast<const uint32_t*>(sB_lo + nr*GP + c0 + 8);
            }

            #pragma unroll
            for (int mf = 0; mf < 4; ++mf)
                #pragma unroll
                for (int nf = 0; nf < 4; ++nf) {
                    mma_bf16(acc[mf][nf], a_hi[mf], b_hi[nf]);
                    mma_bf16(acc[mf][nf], a_hi[mf], b_lo[nf]);
                    mma_bf16(acc[mf][nf], a_lo[mf], b_hi[nf]);
                }
        }
    }

    // Epilogue: d0,d1 -> (row, col..col+1), d2,d3 -> (row+8, ...)
    #pragma unroll
    for (int mf = 0; mf < 4; ++mf) {
        const int mrow = m0 + wm + mf*16 + gid;
        #pragma unroll
        for (int nf = 0; nf < 4; ++nf) {
            const int ncol = j0 + wn + nf*8 + t4*2;
            *reinterpret_cast<float2*>(out + (size_t)mrow*D_ + ncol) =
                make_float2(acc[mf][nf][0], acc[mf][nf][1]);
            *reinterpret_cast<float2*>(out + (size_t)(mrow + 8)*D_ + ncol) =
                make_float2(acc[mf][nf][2], acc[mf][nf][3]);
        }
    }
}

// ---------------------------------------------------------------------------
extern "C" void kernel_launch(void* const* d_in, const int* in_sizes, int n_in,
                              void* d_out, int out_size)
{
    const float* x     = (const float*)d_in[0];
    const float* Wxp   = (const float*)d_in[1];
    const float* Wxb   = (const float*)d_in[2];
    const float* Wdt   = (const float*)d_in[3];
    const float* bdt   = (const float*)d_in[4];
    const float* A_log = (const float*)d_in[5];
    const float* Dskip = (const float*)d_in[6];
    const float* Wout  = (const float*)d_in[7];
    float* out = (float*)d_out;

    const int GEMM_SMEM = 4 * 128 * GP * (int)sizeof(__nv_bfloat16);  // 73728 B
    cudaFuncSetAttribute(gemm_mma_kernel,
                         cudaFuncAttributeMaxDynamicSharedMemorySize, GEMM_SMEM);

    proj_kernel      <<<(B_*L_)/16, 256>>>(x, Wxp, Wxb, Wdt, bdt);
    scan_local_kernel<<<B_*NC,      256>>>(x, A_log, Dskip);
    combine_kernel   <<<(B_*N_*D_)/256, 256>>>();
    correct2_kernel  <<<B_*NC,      256>>>(A_log);
    gemm_mma_kernel  <<<dim3(2, 128), 256, GEMM_SMEM>>>(out, Wout);
}

// round 7
// speedup vs baseline: 1.4909x; 1.0079x over previous
#include <cuda_runtime.h>
#include <cuda_bf16.h>
#include <math.h>
#include <stdint.h>

#define B_    8
#define L_    2048
#define D_    256
#define N_    16
#define R_    16
#define NPROJ 80
#define CL    32          // scan chunk length
#define NC    (L_/CL)     // 64 chunks

typedef unsigned long long ull;

// ---------------- scratch (device globals) ----------------
__device__ float g_delta  [B_*L_*D_];
__device__ float g_delta_b[B_*L_*D_];
__device__ float g_BC     [B_*L_*48];      // Bf(16) Bb(16) C(16)
__device__ float g_pc     [B_*L_*D_];      // cumulative p1 within chunk (fast path)
__device__ float g_P      [B_*NC*N_*D_];
__device__ float g_H      [B_*NC*N_*D_];
__device__ float g_hs     [B_*NC*N_*D_];
__device__ float g_y      [B_*L_*D_];

__device__ __forceinline__ float softplusf(float v) {
    return v > 20.0f ? v : log1pf(__expf(v));
}

// ---------------- packed f32x2 helpers ----------------
__device__ __forceinline__ ull pack2(float lo, float hi) {
    ull r;
    asm("mov.b64 %0, {%1, %2};" : "=l"(r) : "f"(lo), "f"(hi));
    return r;
}
__device__ __forceinline__ void unpack2(ull v, float& lo, float& hi) {
    asm("mov.b64 {%0, %1}, %2;" : "=f"(lo), "=f"(hi) : "l"(v));
}
__device__ __forceinline__ ull mul2(ull a, ull b) {
    ull d;
    asm("mul.rn.f32x2 %0, %1, %2;" : "=l"(d) : "l"(a), "l"(b));
    return d;
}
__device__ __forceinline__ ull fma2(ull a, ull b, ull c) {
    ull d;
    asm("fma.rn.f32x2 %0, %1, %2, %3;" : "=l"(d) : "l"(a), "l"(b), "l"(c));
    return d;
}
// e2[k] = (p^(2k+1), p^(2k+2)), k=0..7
__device__ __forceinline__ void powers16_p2(float p1, ull e2[8]) {
    const float p1sq = p1 * p1;
    e2[0] = pack2(p1, p1sq);
    const ull pstep = pack2(p1sq, p1sq);
    #pragma unroll
    for (int k = 1; k < 8; ++k) e2[k] = mul2(e2[k-1], pstep);
}

// scalar power tree (kept for slow paths / P store)
__device__ __forceinline__ void powers16(float p1, float e[N_]) {
    e[0]  = p1;
    e[1]  = p1 * p1;
    e[2]  = e[1] * p1;
    e[3]  = e[1] * e[1];
    e[4]  = e[3] * p1;
    e[5]  = e[3] * e[1];
    e[6]  = e[3] * e[2];
    e[7]  = e[3] * e[3];
    e[8]  = e[7] * p1;
    e[9]  = e[7] * e[1];
    e[10] = e[7] * e[2];
    e[11] = e[7] * e[3];
    e[12] = e[7] * e[4];
    e[13] = e[7] * e[5];
    e[14] = e[7] * e[6];
    e[15] = e[7] * e[7];
}

__device__ __forceinline__ float check_A(const float* __restrict__ A_log,
                                         int d, bool& fast) {
    float a0 = -__expf(__ldg(A_log + d*N_));
    fast = true;
    #pragma unroll
    for (int n = 1; n < N_; ++n) {
        float an = -__expf(__ldg(A_log + d*N_ + n));
        fast = fast && (fabsf(an - a0*(float)(n+1)) <= 1e-4f*(float)(n+1));
    }
    return a0;
}

// ---------------------------------------------------------------------------
// Kernel 1: fused projections (unchanged).
// ---------------------------------------------------------------------------
__global__ __launch_bounds__(256) void proj_kernel(
    const float* __restrict__ x, const float* __restrict__ Wxp,
    const float* __restrict__ Wxb, const float* __restrict__ Wdt,
    const float* __restrict__ bdt)
{
    const int ROWS = 16;
    __shared__ float sx[ROWS][D_];
    __shared__ float sp[ROWS][NPROJ];
    __shared__ float sWdtT[R_][D_];

    const int row0 = blockIdx.x * ROWS;
    const int tid  = threadIdx.x;

    for (int i = tid; i < D_*R_; i += 256) {
        int d = i / R_, r = i % R_;
        sWdtT[r][d] = Wdt[i];
    }
    for (int i = tid; i < ROWS*D_; i += 256)
        sx[i >> 8][i & 255] = x[row0*D_ + i];
    __syncthreads();

    const int warp = tid >> 5, lane = tid & 31;
    #pragma unroll
    for (int t = 0; t < 10; ++t) {
        int j = warp + 8*t;
        const float* Wrow = (j < 64) ? (Wxp + j*D_) : (Wxb + (j-64)*D_);
        float wv[8];
        #pragma unroll
        for (int k = 0; k < 8; ++k) wv[k] = __ldg(Wrow + lane + 32*k);
        for (int r = 0; r < ROWS; ++r) {
            float acc = 0.f;
            #pragma unroll
            for (int k = 0; k < 8; ++k) acc = fmaf(wv[k], sx[r][lane + 32*k], acc);
            #pragma unroll
            for (int o = 16; o; o >>= 1) acc += __shfl_xor_sync(0xffffffffu, acc, o);
            if (lane == 0) sp[r][j] = acc;
        }
    }
    __syncthreads();

    for (int i = tid; i < ROWS*48; i += 256) {
        int r = i / 48, c = i - r*48;
        g_BC[(row0 + r)*48 + c] = sp[r][16 + c];
    }

    float wdt[R_];
    #pragma unroll
    for (int q = 0; q < R_; ++q) wdt[q] = sWdtT[q][tid];
    const float bv = bdt[tid];

    for (int r = 0; r < ROWS; ++r) {
        float s = bv, sb = bv;
        #pragma unroll
        for (int q = 0; q < R_; ++q) {
            s  = fmaf(sp[r][q],      wdt[q], s);
            sb = fmaf(sp[r][64 + q], wdt[q], sb);
        }
        const int m = row0 + r;
        const int b = m >> 11;
        const int l = m & (L_ - 1);
        g_delta[m*D_ + tid]                              = softplusf(s);
        g_delta_b[((b << 11) + (L_ - 1 - l))*D_ + tid]   = softplusf(sb);
    }
}

// ---------------------------------------------------------------------------
// Kernel 2: scan_local — packed f32x2 fast path.
// ---------------------------------------------------------------------------
__global__ __launch_bounds__(256) void scan_local_kernel(
    const float* __restrict__ x, const float* __restrict__ A_log,
    const float* __restrict__ Dskip)
{
    const int bc = blockIdx.x;
    const int b = bc / NC, c = bc - b*NC;
    const int d = threadIdx.x;
    const int l0 = c * CL;

    __shared__ __align__(16) float sB[CL][48];
    for (int i = d; i < CL*48; i += 256) {
        int t = i / 48, j = i - t*48;
        sB[t][j] = g_BC[(b*L_ + l0 + t)*48 + j];
    }
    __syncthreads();

    bool fast;
    const float a0 = check_A(A_log, d, fast);
    const float dsk = Dskip[d];

    const float* dl_ptr  = g_delta   + (b*L_ + l0)*D_ + d;
    const float* dlb_ptr = g_delta_b + (b*L_ + l0)*D_ + d;
    const float* x_ptr   = x + (b*L_ + l0)*D_ + d;
    const float* xr_ptr  = x + (b*L_ + (L_ - 1 - l0))*D_ + d;
    float* y_ptr  = g_y  + (b*L_ + l0)*D_ + d;
    float* pc_ptr = g_pc + (b*L_ + l0)*D_ + d;

    float* Pp = g_P + ((b*NC + c)*N_)*D_ + d;
    float* Hp = g_H + ((b*NC + c)*N_)*D_ + d;

    if (fast) {
        ull h2[8];
        #pragma unroll
        for (int k = 0; k < 8; ++k) h2[k] = 0ull;
        float p1 = 1.f;

        #pragma unroll
        for (int t0 = 0; t0 < CL; t0 += 4) {
            float dl[4], dlb[4], xv[4], xr[4];
            #pragma unroll
            for (int i = 0; i < 4; ++i) {
                dl[i]  = dl_ptr [(t0+i)*D_];
                dlb[i] = dlb_ptr[(t0+i)*D_];
                xv[i]  = x_ptr  [(t0+i)*D_];
                xr[i]  = xr_ptr [-(t0+i)*D_];
            }
            #pragma unroll
            for (int i = 0; i < 4; ++i) {
                const int t = t0 + i;
                const float e1 = __expf(dl[i] * a0);
                ull e2[8]; powers16_p2(e1, e2);
                const float c1 = dl[i]*xv[i], c2 = dlb[i]*xr[i];
                const ull c1p = pack2(c1, c1);
                const ull c2p = pack2(c2, c2);
                ull y2 = 0ull;
                const ull* Bf2 = reinterpret_cast<const ull*>(&sB[t][0]);
                const ull* Bb2 = reinterpret_cast<const ull*>(&sB[t][16]);
                const ull* C2  = reinterpret_cast<const ull*>(&sB[t][32]);
                #pragma unroll
                for (int k = 0; k < 8; ++k) {
                    const ull du = fma2(c1p, Bf2[k], mul2(c2p, Bb2[k]));
                    h2[k] = fma2(e2[k], h2[k], du);
                    y2    = fma2(h2[k], C2[k], y2);
                }
                p1 *= e1;
                float ylo, yhi; unpack2(y2, ylo, yhi);
                y_ptr [t*D_] = fmaf(xv[i] + xr[i], dsk, ylo + yhi);
                pc_ptr[t*D_] = p1;
            }
        }
        ull pw2[8]; powers16_p2(p1, pw2);
        #pragma unroll
        for (int k = 0; k < 8; ++k) {
            float plo, phi; unpack2(pw2[k], plo, phi);
            float hlo, hhi; unpack2(h2[k], hlo, hhi);
            Pp[(2*k  )*D_] = plo;  Pp[(2*k+1)*D_] = phi;
            Hp[(2*k  )*D_] = hlo;  Hp[(2*k+1)*D_] = hhi;
        }
    } else {
        float h[N_], a[N_], p[N_];
        #pragma unroll
        for (int n = 0; n < N_; ++n) {
            a[n] = -__expf(__ldg(A_log + d*N_ + n));
            p[n] = 1.f;
            h[n] = 0.f;
        }
        for (int t = 0; t < CL; ++t) {
            const float dl  = dl_ptr[t*D_];
            const float dlb = dlb_ptr[t*D_];
            const float xv  = x_ptr[t*D_];
            const float xr  = xr_ptr[-t*D_];
            const float c1 = dl*xv, c2 = dlb*xr;
            float y = 0.f;
            #pragma unroll
            for (int n = 0; n < N_; ++n) {
                const float e = __expf(dl * a[n]);
                h[n] = fmaf(e, h[n], fmaf(c1, sB[t][n], c2 * sB[t][16+n]));
                y    = fmaf(h[n], sB[t][32+n], y);
                p[n] *= e;
            }
            y_ptr[t*D_] = fmaf(xv + xr, dsk, y);
        }
        #pragma unroll
        for (int n = 0; n < N_; ++n) { Pp[n*D_] = p[n]; Hp[n*D_] = h[n]; }
    }
}

// ---------------------------------------------------------------------------
// Kernel 3: sequential combine across chunks — packed over d-pairs.
// Thread = (b, n, d-pair). Grid: B_*N_*D_/2 / 256 = 64 blocks.
// ---------------------------------------------------------------------------
__global__ __launch_bounds__(256) void combine_kernel()
{
    const int idx = blockIdx.x*256 + threadIdx.x;   // 0 .. 16383
    const int dp = idx & 127;                        // d-pair (d = 2*dp)
    const int n = (idx >> 7) & (N_ - 1);
    const int b = idx >> 11;
    const int base = (b*NC*N_ + n)*D_ + 2*dp;
    const int stride = N_*D_;

    const ull* P2 = reinterpret_cast<const ull*>(g_P);
    const ull* H2 = reinterpret_cast<const ull*>(g_H);
    ull* hs2 = reinterpret_cast<ull*>(g_hs);

    ull hs = 0ull;
    #pragma unroll 1
    for (int c0 = 0; c0 < NC; c0 += 8) {
        ull pv[8], hv[8];
        #pragma unroll
        for (int i = 0; i < 8; ++i) {
            pv[i] = P2[(base + (c0+i)*stride) >> 1];
            hv[i] = H2[(base + (c0+i)*stride) >> 1];
        }
        #pragma unroll
        for (int i = 0; i < 8; ++i) {
            hs2[(base + (c0+i)*stride) >> 1] = hs;
            hs = fma2(pv[i], hs, hv[i]);
        }
    }
}

// ---------------------------------------------------------------------------
// Kernel 4: correct2 — packed f32x2 fast path.
// ---------------------------------------------------------------------------
__global__ __launch_bounds__(256) void correct2_kernel(
    const float* __restrict__ A_log)
{
    const int bc = blockIdx.x;
    const int b = bc / NC, c = bc - b*NC;
    const int d = threadIdx.x;
    const int l0 = c * CL;

    __shared__ __align__(16) float sC[CL][N_];
    for (int i = d; i < CL*N_; i += 256) {
        int t = i >> 4, j = i & 15;
        sC[t][j] = g_BC[(b*L_ + l0 + t)*48 + 32 + j];
    }
    __syncthreads();

    bool fast;
    const float a0 = check_A(A_log, d, fast);
    (void)a0;

    float* y_ptr        = g_y  + (b*L_ + l0)*D_ + d;
    const float* pc_ptr = g_pc + (b*L_ + l0)*D_ + d;

    if (fast) {
        ull q2[8];
        #pragma unroll
        for (int k = 0; k < 8; ++k) {
            const float qlo = g_hs[((b*NC + c)*N_ + 2*k  )*D_ + d];
            const float qhi = g_hs[((b*NC + c)*N_ + 2*k+1)*D_ + d];
            q2[k] = pack2(qlo, qhi);
        }
        #pragma unroll
        for (int t0 = 0; t0 < CL; t0 += 4) {
            float p1[4], yl[4];
            #pragma unroll
            for (int i = 0; i < 4; ++i) {
                p1[i] = pc_ptr[(t0+i)*D_];
                yl[i] = y_ptr [(t0+i)*D_];
            }
            #pragma unroll
            for (int i = 0; i < 4; ++i) {
                const int t = t0 + i;
                ull pw2[8]; powers16_p2(p1[i], pw2);
                const ull* C2 = reinterpret_cast<const ull*>(&sC[t][0]);
                ull corr2 = 0ull;
                #pragma unroll
                for (int k = 0; k < 8; ++k)
                    corr2 = fma2(mul2(pw2[k], q2[k]), C2[k], corr2);
                float clo, chi; unpack2(corr2, clo, chi);
                y_ptr[t*D_] = yl[i] + clo + chi;
            }
        }
    } else {
        float q[N_];
        #pragma unroll
        for (int n = 0; n < N_; ++n)
            q[n] = g_hs[((b*NC + c)*N_ + n)*D_ + d];
        const float* dl_ptr = g_delta + (b*L_ + l0)*D_ + d;
        float a[N_];
        #pragma unroll
        for (int n = 0; n < N_; ++n)
            a[n] = -__expf(__ldg(A_log + d*N_ + n));
        for (int t = 0; t < CL; ++t) {
            const float dl = dl_ptr[t*D_];
            float corr = 0.f;
            #pragma unroll
            for (int n = 0; n < N_; ++n) {
                q[n] *= __expf(dl * a[n]);
                corr = fmaf(q[n], sC[t][n], corr);
            }
            y_ptr[t*D_] += corr;
        }
    }
}

// ---------------------------------------------------------------------------
// Kernel 5: out = y @ W_out^T via mma.sync bf16 split (unchanged).
// ---------------------------------------------------------------------------
#define GP 72   // smem pitch in bf16 elements

__device__ __forceinline__ void mma_bf16(float dd[4],
                                         const uint32_t a[4],
                                         const uint32_t b[2]) {
    asm volatile(
        "mma.sync.aligned.m16n8k16.row.col.f32.bf16.bf16.f32 "
        "{%0,%1,%2,%3}, {%4,%5,%6,%7}, {%8,%9}, {%0,%1,%2,%3};"
        : "+f"(dd[0]), "+f"(dd[1]), "+f"(dd[2]), "+f"(dd[3])
        : "r"(a[0]), "r"(a[1]), "r"(a[2]), "r"(a[3]), "r"(b[0]), "r"(b[1]));
}

__global__ __launch_bounds__(256) void gemm_mma_kernel(
    float* __restrict__ out, const float* __restrict__ Wout)
{
    extern __shared__ __nv_bfloat16 sm[];
    __nv_bfloat16* sA_hi = sm;                 // [128][GP]
    __nv_bfloat16* sA_lo = sm + 128*GP;
    __nv_bfloat16* sB_hi = sm + 2*128*GP;
    __nv_bfloat16* sB_lo = sm + 3*128*GP;

    const int tid  = threadIdx.x;
    const int wid  = tid >> 5;
    const int lane = tid & 31;
    const int gid  = lane >> 2;
    const int t4   = lane & 3;

    const int j0 = blockIdx.x * 128;
    const int m0 = blockIdx.y * 128;
    const int wm = (wid >> 2) * 64;
    const int wn = (wid & 3) * 32;

    float acc[4][4][4];
    #pragma unroll
    for (int i = 0; i < 4; ++i)
        #pragma unroll
        for (int j = 0; j < 4; ++j)
            #pragma unroll
            for (int q = 0; q < 4; ++q) acc[i][j][q] = 0.f;

    const int lrow = tid >> 5;
    const int lpc  = tid & 31;

    for (int kc = 0; kc < 256; kc += 64) {
        __syncthreads();
        #pragma unroll
        for (int rr = 0; rr < 16; ++rr) {
            const int row = lrow + rr*8;
            const int soff = row*GP + lpc*2;

            const float2 va = *reinterpret_cast<const float2*>(
                g_y + (m0 + row)*D_ + kc + lpc*2);
            __nv_bfloat16 ahx = __float2bfloat16(va.x);
            __nv_bfloat16 ahy = __float2bfloat16(va.y);
            __nv_bfloat16 alx = __float2bfloat16(va.x - __bfloat162float(ahx));
            __nv_bfloat16 aly = __float2bfloat16(va.y - __bfloat162float(ahy));
            *reinterpret_cast<__nv_bfloat162*>(sA_hi + soff) = __nv_bfloat162(ahx, ahy);
            *reinterpret_cast<__nv_bfloat162*>(sA_lo + soff) = __nv_bfloat162(alx, aly);

            const float2 vb = *reinterpret_cast<const float2*>(
                Wout + (j0 + row)*D_ + kc + lpc*2);
            __nv_bfloat16 bhx = __float2bfloat16(vb.x);
            __nv_bfloat16 bhy = __float2bfloat16(vb.y);
            __nv_bfloat16 blx = __float2bfloat16(vb.x - __bfloat162float(bhx));
            __nv_bfloat16 bly = __float2bfloat16(vb.y - __bfloat162float(bhy));
            *reinterpret_cast<__nv_bfloat162*>(sB_hi + soff) = __nv_bfloat162(bhx, bhy);
            *reinterpret_cast<__nv_bfloat162*>(sB_lo + soff) = __nv_bfloat162(blx, bly);
        }
        __syncthreads();

        #pragma unroll
        for (int ks = 0; ks < 4; ++ks) {
            const int k0 = ks*16;
            uint32_t a_hi[4][4], a_lo[4][4], b_hi[4][2], b_lo[4][2];

            #pragma unroll
            for (int mf = 0; mf < 4; ++mf) {
                const int r0 = wm + mf*16 + gid;
                const int c0 = k0 + t4*2;
                a_hi[mf][0] = *reinterpret_cast<const uint32_t*>(sA_hi + (r0    )*GP + c0    );
                a_hi[mf][1] = *reinterpret_cast<const uint32_t*>(sA_hi + (r0 + 8)*GP + c0    );
                a_hi[mf][2] = *reinterpret_cast<const uint32_t*>(sA_hi + (r0    )*GP + c0 + 8);
                a_hi[mf][3] = *reinterpret_cast<const uint32_t*>(sA_hi + (r0 + 8)*GP + c0 + 8);
                a_lo[mf][0] = *reinterpret_cast<const uint32_t*>(sA_lo + (r0    )*GP + c0    );
                a_lo[mf][1] = *reinterpret_cast<const uint32_t*>(sA_lo + (r0 + 8)*GP + c0    );
                a_lo[mf][2] = *reinterpret_cast<const uint32_t*>(sA_lo + (r0    )*GP + c0 + 8);
                a_lo[mf][3] = *reinterpret_cast<const uint32_t*>(sA_lo + (r0 + 8)*GP + c0 + 8);
            }
            #pragma unroll
            for (int nf = 0; nf < 4; ++nf) {
                const int nr = wn + nf*8 + gid;
                const int c0 = k0 + t4*2;
                b_hi[nf][0] = *reinterpret_cast<const uint32_t*>(sB_hi + nr*GP + c0    );
                b_hi[nf][1] = *reinterpret_cast<const uint32_t*>(sB_hi + nr*GP + c0 + 8);
                b_lo[nf][0] = *reinterpret_cast<const uint32_t*>(sB_lo + nr*GP + c0    );
                b_lo[nf][1] = *reinterpret_cast<const uint32_t*>(sB_lo + nr*GP + c0 + 8);
            }

            #pragma unroll
            for (int mf = 0; mf < 4; ++mf)
                #pragma unroll
                for (int nf = 0; nf < 4; ++nf) {
                    mma_bf16(acc[mf][nf], a_hi[mf], b_hi[nf]);
                    mma_bf16(acc[mf][nf], a_hi[mf], b_lo[nf]);
                    mma_bf16(acc[mf][nf], a_lo[mf], b_hi[nf]);
                }
        }
    }

    #pragma unroll
    for (int mf = 0; mf < 4; ++mf) {
        const int mrow = m0 + wm + mf*16 + gid;
        #pragma unroll
        for (int nf = 0; nf < 4; ++nf) {
            const int ncol = j0 + wn + nf*8 + t4*2;
            *reinterpret_cast<float2*>(out + (size_t)mrow*D_ + ncol) =
                make_float2(acc[mf][nf][0], acc[mf][nf][1]);
            *reinterpret_cast<float2*>(out + (size_t)(mrow + 8)*D_ + ncol) =
                make_float2(acc[mf][nf][2], acc[mf][nf][3]);
        }
    }
}

// ---------------------------------------------------------------------------
extern "C" void kernel_launch(void* const* d_in, const int* in_sizes, int n_in,
                              void* d_out, int out_size)
{
    const float* x     = (const float*)d_in[0];
    const float* Wxp   = (const float*)d_in[1];
    const float* Wxb   = (const float*)d_in[2];
    const float* Wdt   = (const float*)d_in[3];
    const float* bdt   = (const float*)d_in[4];
    const float* A_log = (const float*)d_in[5];
    const float* Dskip = (const float*)d_in[6];
    const float* Wout  = (const float*)d_in[7];
    float* out = (float*)d_out;

    const int GEMM_SMEM = 4 * 128 * GP * (int)sizeof(__nv_bfloat16);  // 73728 B
    cudaFuncSetAttribute(gemm_mma_kernel,
                         cudaFuncAttributeMaxDynamicSharedMemorySize, GEMM_SMEM);

    proj_kernel      <<<(B_*L_)/16, 256>>>(x, Wxp, Wxb, Wdt, bdt);
    scan_local_kernel<<<B_*NC,      256>>>(x, A_log, Dskip);
    combine_kernel   <<<(B_*N_*D_/2)/256, 256>>>();
    correct2_kernel  <<<B_*NC,      256>>>(A_log);
    gemm_mma_kernel  <<<dim3(2, 128), 256, GEMM_SMEM>>>(out, Wout);
}